// round 13
// baseline (speedup 1.0000x reference)
#include <cuda_runtime.h>
#include <math.h>

// Problem dims
#define H   256
#define H2  512
#define B   64
#define L   2048
#define V   32000
#define NG  4               // kA: groups per b
#define NCHG 16             // kA: chunks per group (32 l each)
#define NB7 125             // k7 blocks (V/256)
#define VT7 256
#define WP7 33
#define WBUF7 8448          // 256*33

typedef unsigned long long ull;

// ---------------- scratch (device globals) ----------------------------------------
__device__ __align__(16) float g_w2p[8][H2];
__device__ __align__(16) float g_w2[H2];
__device__ float g_bias;
__device__ __align__(16) float g_ehb[B];
__device__ __align__(16) float g_attn[B * L];        // raw energies
__device__ __align__(16) float g_pm[B * NG];
__device__ __align__(16) float g_ps[B * NG];
__device__ __align__(16) float g_ctxp[B * NG * H];
__device__ __align__(16) float g_xT[H2 * B];         // [emb; ctx] transposed [k][b]
__device__ __align__(16) float g_hT[H * B];          // hidden transposed [k][b]
__device__ __align__(16) float g_yT[H2 * B];         // [h_new; ctx] transposed [k][b]
__device__ __align__(16) float g_logits[B * V];
__device__ __align__(16) float g_lpm[B * 128];
__device__ __align__(16) float g_lps[B * 128];
__device__ __align__(16) float g_lse[B];
__device__ int g_cnt0;
__device__ int g_cntA[B];
__device__ int g_cnt7;

__device__ __forceinline__ ull fma2(ull a, ull x, ull c) {
    asm("fma.rn.f32x2 %0, %1, %2, %3;" : "=l"(a) : "l"(x), "l"(c), "l"(a));
    return a;
}
__device__ __forceinline__ ull pack2(float w) {
    ull r;
    asm("mov.b64 %0, {%1, %1};" : "=l"(r) : "f"(w));
    return r;
}
__device__ __forceinline__ float lo32(ull a) { return __uint_as_float((unsigned)(a & 0xffffffffull)); }
__device__ __forceinline__ float hi32(ull a) { return __uint_as_float((unsigned)(a >> 32)); }
__device__ __forceinline__ void cpasync16(unsigned smem, const void* g) {
    asm volatile("cp.async.ca.shared.global [%0], [%1], 16;" :: "r"(smem), "l"(g));
}
__device__ __forceinline__ void cpasync4(unsigned smem, const void* g) {
    asm volatile("cp.async.ca.shared.global [%0], [%1], 4;" :: "r"(smem), "l"(g));
}
#define CP_COMMIT() asm volatile("cp.async.commit_group;")
#define CP_WAIT0()  asm volatile("cp.async.wait_group 0;")
#define CP_WAIT1()  asm volatile("cp.async.wait_group 1;")

// ---------------- K0: w2 partials + bias + transposes + last-block combine --------
__global__ void k0_prep(const float* __restrict__ attn_W,
                        const float* __restrict__ attn_b,
                        const float* __restrict__ flatten,
                        const float* __restrict__ hidden,
                        const int*   __restrict__ input,
                        const float* __restrict__ emb_table)
{
    __shared__ float s_f[32];
    __shared__ float red[512];
    __shared__ float s_wh[H];
    __shared__ int s_last;
    int blk = blockIdx.x, tid = threadIdx.x;    // 512 threads, 9 blocks

    if (blk < 8) {
        if (tid < 32) s_f[tid] = flatten[blk * 32 + tid];
        __syncthreads();
        float acc = 0.f;
        #pragma unroll 8
        for (int i = 0; i < 32; i++)
            acc += attn_W[(size_t)(blk * 32 + i) * H2 + tid] * s_f[i];
        g_w2p[blk][tid] = acc;
    } else {
        red[tid] = (tid < H) ? flatten[tid] * attn_b[tid] : 0.f;
        __syncthreads();
        for (int s = 256; s > 0; s >>= 1) {
            if (tid < s) red[tid] += red[tid + s];
            __syncthreads();
        }
        if (tid == 0) g_bias = red[0];
        if (tid == 1) g_cnt7 = 0;
        if (tid >= 64 && tid < 128) g_cntA[tid - 64] = 0;
        for (int idx = tid; idx < B * H; idx += 512) {
            int b = idx >> 8, j = idx & 255;
            g_xT[j * B + b] = emb_table[(size_t)input[b] * H + j];
            g_hT[j * B + b] = hidden[idx];
        }
    }

    __threadfence();
    __syncthreads();
    if (tid == 0) s_last = (atomicAdd(&g_cnt0, 1) == 8) ? 1 : 0;
    __syncthreads();
    if (!s_last) return;

    float w = 0.f;
    #pragma unroll
    for (int k = 0; k < 8; k++) w += g_w2p[k][tid];
    g_w2[tid] = w;
    if (tid < H) s_wh[tid] = w;
    __syncthreads();

    int wid = tid >> 5, lane = tid & 31;        // 16 warps x 4 b
    float bias = g_bias;
    #pragma unroll
    for (int i = 0; i < 4; i++) {
        int b = wid * 4 + i;
        float a = 0.f;
        #pragma unroll
        for (int c = 0; c < 8; c++) {
            int k = c * 32 + lane;
            a += hidden[b * H + k] * s_wh[k];
        }
        #pragma unroll
        for (int o = 16; o > 0; o >>= 1) a += __shfl_down_sync(0xffffffffu, a, o);
        if (lane == 0) g_ehb[b] = a + bias;
    }
    if (tid == 0) g_cnt0 = 0;                   // reset for graph replay
}

// ---------------- KA: pipelined energies + online-softmax ctx + fused combine -----
__global__ __launch_bounds__(256) void kA_attn(const float* __restrict__ enc,
                                               float* __restrict__ out_attn)
{
    extern __shared__ float sm[];
    float* s_w2 = sm + 16384;        // 256
    float* s_e  = s_w2 + H;          // 32
    float* s_w  = s_e + 32;          // 32
    float* s_st = s_w + 32;          // state + combine scratch
    int*   s_fl = (int*)(s_st + 12);

    int b = blockIdx.x >> 2;
    int g = blockIdx.x & 3;
    int tid = threadIdx.x;
    int wid = tid >> 5, lane = tid & 31;

    unsigned tb = (unsigned)__cvta_generic_to_shared(sm);
    const float4* src0 = (const float4*)(enc + (size_t)b * H);

    {
        int l0 = (g * NCHG) * 32;
        #pragma unroll
        for (int i = 0; i < 8; i++) {
            int idx = tid + 256 * i;
            int row = idx >> 6, col = idx & 63;
            cpasync16(tb + (unsigned)idx * 16, src0 + (size_t)(l0 + row) * 4096 + col);
        }
        CP_COMMIT();
    }
    s_w2[tid] = g_w2[H + tid];
    if (tid == 0) { s_st[0] = -INFINITY; s_st[1] = 0.f; }
    float ehb = g_ehb[b];
    float ctx_acc = 0.f;

    for (int i = 0; i < NCHG; i++) {
        if (i < NCHG - 1) {
            int l0 = (g * NCHG + i + 1) * 32;
            unsigned dst = tb + (unsigned)(((i + 1) & 1) * 8192) * 4;
            #pragma unroll
            for (int t = 0; t < 8; t++) {
                int idx = tid + 256 * t;
                int row = idx >> 6, col = idx & 63;
                cpasync16(dst + (unsigned)idx * 16, src0 + (size_t)(l0 + row) * 4096 + col);
            }
            CP_COMMIT();
            CP_WAIT1();
        } else {
            CP_WAIT0();
        }
        __syncthreads();

        float* tile = sm + (i & 1) * 8192;
        int l0 = (g * NCHG + i) * 32;

        #pragma unroll
        for (int r = 0; r < 4; r++) {
            int l = wid * 4 + r;
            const float4* tr = (const float4*)(tile + l * H);
            const float4* w4 = (const float4*)s_w2;
            float4 t0 = tr[lane],      w0 = w4[lane];
            float4 t1 = tr[32 + lane], w1 = w4[32 + lane];
            float a = t0.x * w0.x + t0.y * w0.y + t0.z * w0.z + t0.w * w0.w
                    + t1.x * w1.x + t1.y * w1.y + t1.z * w1.z + t1.w * w1.w;
            #pragma unroll
            for (int o = 16; o > 0; o >>= 1) a += __shfl_down_sync(0xffffffffu, a, o);
            if (lane == 0) {
                float e = a + ehb;
                s_e[l] = e;
                g_attn[b * L + l0 + l] = e;
            }
        }
        __syncthreads();

        if (wid == 0) {
            float m = s_e[lane];
            #pragma unroll
            for (int o = 16; o > 0; o >>= 1) m = fmaxf(m, __shfl_xor_sync(0xffffffffu, m, o));
            if (lane == 0) {
                float m_new = fmaxf(s_st[0], m);
                s_st[2] = m_new;
                s_st[3] = __expf(s_st[0] - m_new);
                s_st[0] = m_new;
            }
        }
        __syncthreads();
        float m_new = s_st[2], sc_old = s_st[3];
        if (tid < 32) s_w[tid] = __expf(s_e[tid] - m_new);
        __syncthreads();
        if (wid == 0) {
            float s = s_w[lane];
            #pragma unroll
            for (int o = 16; o > 0; o >>= 1) s += __shfl_xor_sync(0xffffffffu, s, o);
            if (lane == 0) s_st[1] = s_st[1] * sc_old + s;
        }

        float a0 = 0.f, a1 = 0.f, a2 = 0.f, a3 = 0.f;
        #pragma unroll
        for (int l = 0; l < 32; l += 4) {
            a0 += s_w[l + 0] * tile[(l + 0) * H + tid];
            a1 += s_w[l + 1] * tile[(l + 1) * H + tid];
            a2 += s_w[l + 2] * tile[(l + 2) * H + tid];
            a3 += s_w[l + 3] * tile[(l + 3) * H + tid];
        }
        ctx_acc = ctx_acc * sc_old + ((a0 + a1) + (a2 + a3));
    }

    g_ctxp[(size_t)(b * NG + g) * H + tid] = ctx_acc;
    if (tid == 0) { g_pm[b * NG + g] = s_st[0]; g_ps[b * NG + g] = s_st[1]; }

    __threadfence();
    __syncthreads();
    if (tid == 0) s_fl[0] = (atomicAdd(&g_cntA[b], 1) == NG - 1) ? 1 : 0;
    __syncthreads();
    if (!s_fl[0]) return;

    if (tid == 0) {
        float m0 = g_pm[b * NG + 0], m1 = g_pm[b * NG + 1];
        float m2 = g_pm[b * NG + 2], m3 = g_pm[b * NG + 3];
        float m = fmaxf(fmaxf(m0, m1), fmaxf(m2, m3));
        float sc0 = __expf(m0 - m), sc1 = __expf(m1 - m);
        float sc2 = __expf(m2 - m), sc3 = __expf(m3 - m);
        float ssum = g_ps[b * NG + 0] * sc0 + g_ps[b * NG + 1] * sc1
                   + g_ps[b * NG + 2] * sc2 + g_ps[b * NG + 3] * sc3;
        s_st[4] = sc0; s_st[5] = sc1; s_st[6] = sc2; s_st[7] = sc3;
        s_st[8] = m; s_st[9] = 1.f / ssum;
    }
    __syncthreads();
    float mg = s_st[8], inv = s_st[9];

    float acc = s_st[4] * g_ctxp[(size_t)(b * NG + 0) * H + tid]
              + s_st[5] * g_ctxp[(size_t)(b * NG + 1) * H + tid]
              + s_st[6] * g_ctxp[(size_t)(b * NG + 2) * H + tid]
              + s_st[7] * g_ctxp[(size_t)(b * NG + 3) * H + tid];
    float ctxv = acc * inv;
    g_xT[(H + tid) * B + b] = ctxv;
    g_yT[(H + tid) * B + b] = ctxv;

    if (out_attn)
        for (int l = tid; l < L; l += 256)
            out_attn[b * L + l] = __expf(g_attn[b * L + l] - mg) * inv;
}

// ---------------- K56-v3: GRU, block per j, 8 warps split k, lanes = b-pairs ------
__global__ __launch_bounds__(256) void k56_gru(const float* __restrict__ Wih,
                                               const float* __restrict__ Whh,
                                               const float* __restrict__ bih,
                                               const float* __restrict__ bhh,
                                               float* __restrict__ out_h)
{
    __shared__ float s_px[8][3][64];            // warp, gate, b
    int j = blockIdx.x;                         // 0..255
    int tid = threadIdx.x;
    int wid = tid >> 5, lane = tid & 31;

    ull ar = 0, az = 0, an = 0;
    if (wid < 4) {
        int k0 = wid * 128;
        const float* wr = Wih + (size_t)j * H2 + k0;
        const float* wz = Wih + (size_t)(j + H) * H2 + k0;
        const float* wn = Wih + (size_t)(j + 2 * H) * H2 + k0;
        const float* xp = g_xT + k0 * B + lane * 2;
        #pragma unroll 8
        for (int k = 0; k < 128; k++) {
            ull x2 = *(const ull*)(xp + k * B);
            ar = fma2(ar, pack2(wr[k]), x2);
            az = fma2(az, pack2(wz[k]), x2);
            an = fma2(an, pack2(wn[k]), x2);
        }
    } else {
        int k0 = (wid - 4) * 64;
        const float* wr = Whh + (size_t)j * H + k0;
        const float* wz = Whh + (size_t)(j + H) * H + k0;
        const float* wn = Whh + (size_t)(j + 2 * H) * H + k0;
        const float* hp = g_hT + k0 * B + lane * 2;
        #pragma unroll 8
        for (int k = 0; k < 64; k++) {
            ull h2 = *(const ull*)(hp + k * B);
            ar = fma2(ar, pack2(wr[k]), h2);
            az = fma2(az, pack2(wz[k]), h2);
            an = fma2(an, pack2(wn[k]), h2);
        }
    }
    s_px[wid][0][lane * 2] = lo32(ar); s_px[wid][0][lane * 2 + 1] = hi32(ar);
    s_px[wid][1][lane * 2] = lo32(az); s_px[wid][1][lane * 2 + 1] = hi32(az);
    s_px[wid][2][lane * 2] = lo32(an); s_px[wid][2][lane * 2 + 1] = hi32(an);
    __syncthreads();

    if (wid != 0) return;
    float bir = bih[j], biz = bih[j + H], bin = bih[j + 2 * H];
    float bhr = bhh[j], bhz = bhh[j + H], bhn = bhh[j + 2 * H];
    float2 hp2 = *(const float2*)(g_hT + j * B + lane * 2);

    float hn_out[2];
    #pragma unroll
    for (int d = 0; d < 2; d++) {
        int bb = lane * 2 + d;
        float gir = s_px[0][0][bb] + s_px[1][0][bb] + s_px[2][0][bb] + s_px[3][0][bb] + bir;
        float giz = s_px[0][1][bb] + s_px[1][1][bb] + s_px[2][1][bb] + s_px[3][1][bb] + biz;
        float gin = s_px[0][2][bb] + s_px[1][2][bb] + s_px[2][2][bb] + s_px[3][2][bb] + bin;
        float ghr = s_px[4][0][bb] + s_px[5][0][bb] + s_px[6][0][bb] + s_px[7][0][bb] + bhr;
        float ghz = s_px[4][1][bb] + s_px[5][1][bb] + s_px[6][1][bb] + s_px[7][1][bb] + bhz;
        float ghn = s_px[4][2][bb] + s_px[5][2][bb] + s_px[6][2][bb] + s_px[7][2][bb] + bhn;
        float r = 1.f / (1.f + __expf(-(gir + ghr)));
        float z = 1.f / (1.f + __expf(-(giz + ghz)));
        float n = tanhf(gin + r * ghn);
        float hprev = d ? hp2.y : hp2.x;
        hn_out[d] = (1.f - z) * n + z * hprev;
    }
    *(float2*)(g_yT + j * B + lane * 2) = make_float2(hn_out[0], hn_out[1]);
    if (out_h) {
        out_h[(lane * 2 + 0) * H + j] = hn_out[0];
        out_h[(lane * 2 + 1) * H + j] = hn_out[1];
    }
}

// ---------------- K7: logits GEMM, 1024 threads (32 warps/SM), tile 2v x 8b -------
// 125 blocks x (256v x 64b). y resident (128KB), W double-buffered pitch 33.
#define SOP7 257
__global__ __launch_bounds__(1024, 1) void k7_logits(const float* __restrict__ outW,
                                                     const float* __restrict__ outb)
{
    extern __shared__ float sm[];
    float* s_y = sm;                             // 32768 floats (128KB)
    float* s_w = sm + 32768;                     // 2 x 8448 floats (~67.6KB)
    int tid = threadIdx.x;
    int v0b = blockIdx.x * VT7;

    unsigned syb = (unsigned)__cvta_generic_to_shared(s_y);
    unsigned swb = (unsigned)__cvta_generic_to_shared(s_w);

    // W chunk staging: 8192 scalars, 8/thread, 4-byte cp.async
    #define K7_ISSUE_W(cc, buf) do {                                             \
        int _c = (cc), _bf = (buf);                                              \
        _Pragma("unroll")                                                        \
        for (int t = 0; t < 8; t++) {                                            \
            int idx = tid + 1024 * t;                                            \
            int row = idx >> 5, k = idx & 31;                                    \
            cpasync4(swb + (unsigned)(_bf * WBUF7 + row * WP7 + k) * 4,          \
                     outW + (size_t)(v0b + row) * H2 + _c * 32 + k);             \
        }                                                                        \
    } while (0)

    // prologue: full y (8192 f4, 8/thread) + W chunk 0, one group
    #pragma unroll
    for (int t = 0; t < 8; t++) {
        int idx = tid + 1024 * t;
        cpasync16(syb + (unsigned)idx * 16, g_yT + idx * 4);
    }
    K7_ISSUE_W(0, 0);
    CP_COMMIT();

    int bg = tid & 7;                            // 8 b-groups of 8
    int tv = tid >> 3;                           // 128 v-groups of 2
    int vl = tv * 2;
    int b0 = bg * 8;

    ull acc[2][4];
    #pragma unroll
    for (int i = 0; i < 2; i++)
        #pragma unroll
        for (int p = 0; p < 4; p++) acc[i][p] = 0ull;

    for (int c = 0; c < 16; c++) {
        if (c < 15) { K7_ISSUE_W(c + 1, (c + 1) & 1); CP_COMMIT(); CP_WAIT1(); }
        else        { CP_WAIT0(); }
        __syncthreads();

        const float* wb = s_w + (c & 1) * WBUF7;
        #pragma unroll 4
        for (int kk = 0; kk < 32; kk++) {
            int k = c * 32 + kk;
            ulonglong2 ya = *(const ulonglong2*)(s_y + k * 64 + b0);
            ulonglong2 yc = *(const ulonglong2*)(s_y + k * 64 + b0 + 4);
            #pragma unroll
            for (int i = 0; i < 2; i++) {
                ull w2 = pack2(wb[(vl + i) * WP7 + kk]);
                acc[i][0] = fma2(acc[i][0], w2, ya.x);
                acc[i][1] = fma2(acc[i][1], w2, ya.y);
                acc[i][2] = fma2(acc[i][2], w2, yc.x);
                acc[i][3] = fma2(acc[i][3], w2, yc.y);
            }
        }
    }
    __syncthreads();                             // all reads of s_y done

    // epilogue: stage 64b x 256v tile (pitch 257), add bias
    float* s_out = sm;
    #pragma unroll
    for (int i = 0; i < 2; i++) {
        float bb = outb[v0b + vl + i];
        #pragma unroll
        for (int p = 0; p < 4; p++) {
            s_out[(b0 + 2 * p + 0) * SOP7 + vl + i] = lo32(acc[i][p]) + bb;
            s_out[(b0 + 2 * p + 1) * SOP7 + vl + i] = hi32(acc[i][p]) + bb;
        }
    }
    __syncthreads();

    // coalesced float4 copy: 4096 f4, 4/thread
    #pragma unroll
    for (int t = 0; t < 4; t++) {
        int i = tid + 1024 * t;
        int v4 = i & 63, b = i >> 6;
        const float* s = s_out + b * SOP7 + v4 * 4;
        *(float4*)(g_logits + (size_t)b * V + v0b + v4 * 4)
            = make_float4(s[0], s[1], s[2], s[3]);
    }

    // lse partials: 16 threads per b, 16 v each
    int bq = tid >> 4, i16 = tid & 15;
    {
        const float* rr = s_out + bq * SOP7 + i16 * 16;
        float m = -INFINITY;
        #pragma unroll
        for (int j = 0; j < 16; j++) m = fmaxf(m, rr[j]);
        #pragma unroll
        for (int o = 8; o > 0; o >>= 1) m = fmaxf(m, __shfl_xor_sync(0xffffffffu, m, o));
        float s = 0.f;
        #pragma unroll
        for (int j = 0; j < 16; j++) s += __expf(rr[j] - m);
        #pragma unroll
        for (int o = 8; o > 0; o >>= 1) s += __shfl_xor_sync(0xffffffffu, s, o);
        if (i16 == 0) {
            g_lpm[bq * 128 + blockIdx.x] = m;
            g_lps[bq * 128 + blockIdx.x] = s;
        }
    }

    // last block merges lse
    __shared__ int s_last;
    __threadfence();
    __syncthreads();
    if (tid == 0) s_last = (atomicAdd(&g_cnt7, 1) == NB7 - 1) ? 1 : 0;
    __syncthreads();
    if (!s_last) return;

    float m = -INFINITY;
    for (int i = i16; i < NB7; i += 16) m = fmaxf(m, g_lpm[bq * 128 + i]);
    #pragma unroll
    for (int o = 8; o > 0; o >>= 1) m = fmaxf(m, __shfl_xor_sync(0xffffffffu, m, o));
    float s = 0.f;
    for (int i = i16; i < NB7; i += 16)
        s += g_lps[bq * 128 + i] * __expf(g_lpm[bq * 128 + i] - m);
    #pragma unroll
    for (int o = 8; o > 0; o >>= 1) s += __shfl_xor_sync(0xffffffffu, s, o);
    if (i16 == 0) g_lse[bq] = m + logf(s);
}

// ---------------- K8w: out = logits - lse[b] ---------------------------------------
__global__ void k8w_write(float* __restrict__ out)
{
    int idx = blockIdx.x * 256 + threadIdx.x;   // float4 index
    int b = idx / (V / 4);
    float lse = g_lse[b];
    float4 v = ((const float4*)g_logits)[idx];
    v.x -= lse; v.y -= lse; v.z -= lse; v.w -= lse;
    ((float4*)out)[idx] = v;
}

// ---------------- host launch ------------------------------------------------------
extern "C" void kernel_launch(void* const* d_in, const int* in_sizes, int n_in,
                              void* d_out, int out_size)
{
    int s = (n_in >= 14 && in_sizes[3] == 1) ? 0 : -1;
    const int*   input    = (const int*)  d_in[0];
    const float* hidden   = (const float*)d_in[1];
    const float* enc      = (const float*)d_in[2];
    const float* emb      = (const float*)d_in[4 + s];
    const float* attn_W   = (const float*)d_in[5 + s];
    const float* attn_b   = (const float*)d_in[6 + s];
    const float* flatten  = (const float*)d_in[7 + s];
    const float* Wih      = (const float*)d_in[8 + s];
    const float* Whh      = (const float*)d_in[9 + s];
    const float* bih      = (const float*)d_in[10 + s];
    const float* bhh      = (const float*)d_in[11 + s];
    const float* outW     = (const float*)d_in[12 + s];
    const float* outb     = (const float*)d_in[13 + s];

    float* dout     = (float*)d_out;
    float* out_h    = (out_size >= B * V + B * H) ? dout + B * V : nullptr;
    float* out_attn = (out_size >= B * V + B * H + B * L) ? dout + B * V + B * H : nullptr;

    k0_prep<<<9, 512>>>(attn_W, attn_b, flatten, hidden, input, emb);

    int smem_kA = (16384 + 256 + 32 + 32 + 16) * (int)sizeof(float);  // ~66.9KB
    cudaFuncSetAttribute(kA_attn, cudaFuncAttributeMaxDynamicSharedMemorySize, smem_kA);
    kA_attn<<<B * NG, 256, smem_kA>>>(enc, out_attn);

    k56_gru<<<256, 256>>>(Wih, Whh, bih, bhh, out_h);

    int smem_k7 = (32768 + 2 * WBUF7) * (int)sizeof(float);          // 198656 B
    cudaFuncSetAttribute(k7_logits, cudaFuncAttributeMaxDynamicSharedMemorySize, smem_k7);
    k7_logits<<<NB7, 1024, smem_k7>>>(outW, outb);

    k8w_write<<<(B * V / 4) / 256, 256>>>(dout);
}

// round 14
// speedup vs baseline: 1.3097x; 1.3097x over previous
#include <cuda_runtime.h>
#include <math.h>

// Problem dims
#define H   256
#define H2  512
#define B   64
#define L   2048
#define V   32000
#define NG  8               // kA: groups per b
#define NCHG 8              // kA: chunks per group (32 l each)
#define NB7V 125            // k7: v tiles
#define VT7 256             // k7: v per tile
#define KH  256             // k7: k per half
#define KCH 16              // k7: k per W chunk
#define NCH7 16             // k7: chunks per half
#define WP7 17
#define WBUF7 (256 * 17)    // 4352 floats

typedef unsigned long long ull;

// ---------------- scratch (device globals) ----------------------------------------
__device__ __align__(16) float g_w2p[8][H2];
__device__ __align__(16) float g_w2[H2];
__device__ float g_bias;
__device__ __align__(16) float g_ehb[B];
__device__ __align__(16) float g_attn[B * L];        // raw energies
__device__ __align__(16) float g_pm[B * NG];
__device__ __align__(16) float g_ps[B * NG];
__device__ __align__(16) float g_ctxp[B * NG * H];
__device__ __align__(16) float g_xT[H2 * B];         // [emb; ctx] transposed [k][b]
__device__ __align__(16) float g_hT[H * B];          // hidden transposed [k][b]
__device__ __align__(16) float g_yT[H2 * B];         // [h_new; ctx] transposed [k][b]
__device__ __align__(16) float g_part[250 * VT7 * B]; // k7 half-partials [blk][b][v]
__device__ __align__(16) float g_logits[B * V];
__device__ __align__(16) float g_lpm[B * 128];
__device__ __align__(16) float g_lps[B * 128];
__device__ __align__(16) float g_lse[B];
__device__ int g_cnt0;
__device__ int g_cntA[B];
__device__ int g_cntV[NB7V];
__device__ int g_cnt7;

__device__ __forceinline__ ull fma2(ull a, ull x, ull c) {
    asm("fma.rn.f32x2 %0, %1, %2, %3;" : "=l"(a) : "l"(x), "l"(c), "l"(a));
    return a;
}
__device__ __forceinline__ ull pack2(float w) {
    ull r;
    asm("mov.b64 %0, {%1, %1};" : "=l"(r) : "f"(w));
    return r;
}
__device__ __forceinline__ float lo32(ull a) { return __uint_as_float((unsigned)(a & 0xffffffffull)); }
__device__ __forceinline__ float hi32(ull a) { return __uint_as_float((unsigned)(a >> 32)); }
__device__ __forceinline__ void cpasync16(unsigned smem, const void* g) {
    asm volatile("cp.async.ca.shared.global [%0], [%1], 16;" :: "r"(smem), "l"(g));
}
__device__ __forceinline__ void cpasync4(unsigned smem, const void* g) {
    asm volatile("cp.async.ca.shared.global [%0], [%1], 4;" :: "r"(smem), "l"(g));
}
#define CP_COMMIT() asm volatile("cp.async.commit_group;")
#define CP_WAIT0()  asm volatile("cp.async.wait_group 0;")

// ---------------- K0: w2 partials + bias + transposes + last-block combine --------
__global__ void k0_prep(const float* __restrict__ attn_W,
                        const float* __restrict__ attn_b,
                        const float* __restrict__ flatten,
                        const float* __restrict__ hidden,
                        const int*   __restrict__ input,
                        const float* __restrict__ emb_table)
{
    __shared__ float s_f[32];
    __shared__ float red[512];
    __shared__ float s_wh[H];
    __shared__ int s_last;
    int blk = blockIdx.x, tid = threadIdx.x;    // 512 threads, 9 blocks

    if (blk < 8) {
        if (tid < 32) s_f[tid] = flatten[blk * 32 + tid];
        __syncthreads();
        float acc = 0.f;
        #pragma unroll 8
        for (int i = 0; i < 32; i++)
            acc += attn_W[(size_t)(blk * 32 + i) * H2 + tid] * s_f[i];
        g_w2p[blk][tid] = acc;
    } else {
        red[tid] = (tid < H) ? flatten[tid] * attn_b[tid] : 0.f;
        __syncthreads();
        for (int s = 256; s > 0; s >>= 1) {
            if (tid < s) red[tid] += red[tid + s];
            __syncthreads();
        }
        if (tid == 0) g_bias = red[0];
        if (tid == 1) g_cnt7 = 0;
        if (tid >= 64 && tid < 128) g_cntA[tid - 64] = 0;
        if (tid >= 128 && tid < 128 + NB7V) g_cntV[tid - 128] = 0;
        for (int idx = tid; idx < B * H; idx += 512) {
            int b = idx >> 8, j = idx & 255;
            g_xT[j * B + b] = emb_table[(size_t)input[b] * H + j];
            g_hT[j * B + b] = hidden[idx];
        }
    }

    __threadfence();
    __syncthreads();
    if (tid == 0) s_last = (atomicAdd(&g_cnt0, 1) == 8) ? 1 : 0;
    __syncthreads();
    if (!s_last) return;

    float w = 0.f;
    #pragma unroll
    for (int k = 0; k < 8; k++) w += g_w2p[k][tid];
    g_w2[tid] = w;
    if (tid < H) s_wh[tid] = w;
    __syncthreads();

    int wid = tid >> 5, lane = tid & 31;        // 16 warps x 4 b
    float bias = g_bias;
    #pragma unroll
    for (int i = 0; i < 4; i++) {
        int b = wid * 4 + i;
        float a = 0.f;
        #pragma unroll
        for (int c = 0; c < 8; c++) {
            int k = c * 32 + lane;
            a += hidden[b * H + k] * s_wh[k];
        }
        #pragma unroll
        for (int o = 16; o > 0; o >>= 1) a += __shfl_down_sync(0xffffffffu, a, o);
        if (lane == 0) g_ehb[b] = a + bias;
    }
    if (tid == 0) g_cnt0 = 0;                   // reset for graph replay
}

// ---------------- KA: pipelined energies + online-softmax ctx + fused combine -----
// 512 blocks (b x 8 groups), 8 chunks of 32 l each. Issue AFTER sync (race fix).
__global__ __launch_bounds__(256) void kA_attn(const float* __restrict__ enc,
                                               float* __restrict__ out_attn)
{
    extern __shared__ float sm[];
    float* s_w2 = sm + 16384;        // 256
    float* s_e  = s_w2 + H;          // 32
    float* s_w  = s_e + 32;          // 32
    float* s_st = s_w + 32;          // [0]=m_run [1]=s_run [2]=m_new [3]=sc_old
                                     // [4..11]=combine scales [12]=mg [13]=inv
    int*   s_fl = (int*)(s_st + 16);

    int b = blockIdx.x >> 3;
    int g = blockIdx.x & 7;
    int tid = threadIdx.x;
    int wid = tid >> 5, lane = tid & 31;

    unsigned tb = (unsigned)__cvta_generic_to_shared(sm);
    const float4* src0 = (const float4*)(enc + (size_t)b * H);

    // prologue: chunk 0 into buf 0
    {
        int l0 = g * (NCHG * 32);
        #pragma unroll
        for (int i = 0; i < 8; i++) {
            int idx = tid + 256 * i;
            int row = idx >> 6, col = idx & 63;
            cpasync16(tb + (unsigned)idx * 16, src0 + (size_t)(l0 + row) * 4096 + col);
        }
        CP_COMMIT();
    }
    s_w2[tid] = g_w2[H + tid];
    if (tid == 0) { s_st[0] = -INFINITY; s_st[1] = 0.f; }
    float ehb = g_ehb[b];
    float ctx_acc = 0.f;

    for (int i = 0; i < NCHG; i++) {
        CP_WAIT0();                 // chunk i landed
        __syncthreads();            // all threads past chunk i-1 compute
        if (i + 1 < NCHG) {         // safe: buf (i+1)&1 no longer read by anyone
            int l0 = g * (NCHG * 32) + (i + 1) * 32;
            unsigned dst = tb + (unsigned)(((i + 1) & 1) * 8192) * 4;
            #pragma unroll
            for (int t = 0; t < 8; t++) {
                int idx = tid + 256 * t;
                int row = idx >> 6, col = idx & 63;
                cpasync16(dst + (unsigned)idx * 16, src0 + (size_t)(l0 + row) * 4096 + col);
            }
            CP_COMMIT();
        }

        float* tile = sm + (i & 1) * 8192;
        int l0 = g * (NCHG * 32) + i * 32;

        // energies: 8 warps x 4 l
        #pragma unroll
        for (int r = 0; r < 4; r++) {
            int l = wid * 4 + r;
            const float4* tr = (const float4*)(tile + l * H);
            const float4* w4 = (const float4*)s_w2;
            float4 t0 = tr[lane],      w0 = w4[lane];
            float4 t1 = tr[32 + lane], w1 = w4[32 + lane];
            float a = t0.x * w0.x + t0.y * w0.y + t0.z * w0.z + t0.w * w0.w
                    + t1.x * w1.x + t1.y * w1.y + t1.z * w1.z + t1.w * w1.w;
            #pragma unroll
            for (int o = 16; o > 0; o >>= 1) a += __shfl_down_sync(0xffffffffu, a, o);
            if (lane == 0) {
                float e = a + ehb;
                s_e[l] = e;
                g_attn[b * L + l0 + l] = e;
            }
        }
        __syncthreads();

        if (wid == 0) {
            float m = s_e[lane];
            #pragma unroll
            for (int o = 16; o > 0; o >>= 1) m = fmaxf(m, __shfl_xor_sync(0xffffffffu, m, o));
            if (lane == 0) {
                float m_new = fmaxf(s_st[0], m);
                s_st[2] = m_new;
                s_st[3] = __expf(s_st[0] - m_new);
                s_st[0] = m_new;
            }
        }
        __syncthreads();
        float m_new = s_st[2], sc_old = s_st[3];
        if (tid < 32) s_w[tid] = __expf(s_e[tid] - m_new);
        __syncthreads();
        if (wid == 0) {
            float s = s_w[lane];
            #pragma unroll
            for (int o = 16; o > 0; o >>= 1) s += __shfl_xor_sync(0xffffffffu, s, o);
            if (lane == 0) s_st[1] = s_st[1] * sc_old + s;
        }

        float a0 = 0.f, a1 = 0.f, a2 = 0.f, a3 = 0.f;
        #pragma unroll
        for (int l = 0; l < 32; l += 4) {
            a0 += s_w[l + 0] * tile[(l + 0) * H + tid];
            a1 += s_w[l + 1] * tile[(l + 1) * H + tid];
            a2 += s_w[l + 2] * tile[(l + 2) * H + tid];
            a3 += s_w[l + 3] * tile[(l + 3) * H + tid];
        }
        ctx_acc = ctx_acc * sc_old + ((a0 + a1) + (a2 + a3));
    }

    g_ctxp[(size_t)(b * NG + g) * H + tid] = ctx_acc;
    if (tid == 0) { g_pm[b * NG + g] = s_st[0]; g_ps[b * NG + g] = s_st[1]; }

    __threadfence();
    __syncthreads();
    if (tid == 0) s_fl[0] = (atomicAdd(&g_cntA[b], 1) == NG - 1) ? 1 : 0;
    __syncthreads();
    if (!s_fl[0]) return;

    if (tid == 0) {
        float mm[NG], m = -INFINITY;
        #pragma unroll
        for (int gg = 0; gg < NG; gg++) { mm[gg] = g_pm[b * NG + gg]; m = fmaxf(m, mm[gg]); }
        float ssum = 0.f;
        #pragma unroll
        for (int gg = 0; gg < NG; gg++) {
            float sc = __expf(mm[gg] - m);
            s_st[4 + gg] = sc;
            ssum += g_ps[b * NG + gg] * sc;
        }
        s_st[12] = m; s_st[13] = 1.f / ssum;
    }
    __syncthreads();
    float mg = s_st[12], inv = s_st[13];

    float acc = 0.f;
    #pragma unroll
    for (int gg = 0; gg < NG; gg++)
        acc += s_st[4 + gg] * g_ctxp[(size_t)(b * NG + gg) * H + tid];
    float ctxv = acc * inv;
    g_xT[(H + tid) * B + b] = ctxv;
    g_yT[(H + tid) * B + b] = ctxv;

    if (out_attn)
        for (int l = tid; l < L; l += 256)
            out_attn[b * L + l] = __expf(g_attn[b * L + l] - mg) * inv;
}

// ---------------- K56: GRU, block per j, 8 warps split k, lanes = b-pairs ---------
__global__ __launch_bounds__(256) void k56_gru(const float* __restrict__ Wih,
                                               const float* __restrict__ Whh,
                                               const float* __restrict__ bih,
                                               const float* __restrict__ bhh,
                                               float* __restrict__ out_h)
{
    __shared__ float s_px[8][3][64];            // warp, gate, b
    int j = blockIdx.x;                         // 0..255
    int tid = threadIdx.x;
    int wid = tid >> 5, lane = tid & 31;

    ull ar = 0, az = 0, an = 0;
    if (wid < 4) {
        int k0 = wid * 128;
        const float* wr = Wih + (size_t)j * H2 + k0;
        const float* wz = Wih + (size_t)(j + H) * H2 + k0;
        const float* wn = Wih + (size_t)(j + 2 * H) * H2 + k0;
        const float* xp = g_xT + k0 * B + lane * 2;
        #pragma unroll 8
        for (int k = 0; k < 128; k++) {
            ull x2 = *(const ull*)(xp + k * B);
            ar = fma2(ar, pack2(wr[k]), x2);
            az = fma2(az, pack2(wz[k]), x2);
            an = fma2(an, pack2(wn[k]), x2);
        }
    } else {
        int k0 = (wid - 4) * 64;
        const float* wr = Whh + (size_t)j * H + k0;
        const float* wz = Whh + (size_t)(j + H) * H + k0;
        const float* wn = Whh + (size_t)(j + 2 * H) * H + k0;
        const float* hp = g_hT + k0 * B + lane * 2;
        #pragma unroll 8
        for (int k = 0; k < 64; k++) {
            ull h2 = *(const ull*)(hp + k * B);
            ar = fma2(ar, pack2(wr[k]), h2);
            az = fma2(az, pack2(wz[k]), h2);
            an = fma2(an, pack2(wn[k]), h2);
        }
    }
    s_px[wid][0][lane * 2] = lo32(ar); s_px[wid][0][lane * 2 + 1] = hi32(ar);
    s_px[wid][1][lane * 2] = lo32(az); s_px[wid][1][lane * 2 + 1] = hi32(az);
    s_px[wid][2][lane * 2] = lo32(an); s_px[wid][2][lane * 2 + 1] = hi32(an);
    __syncthreads();

    if (wid != 0) return;
    float bir = bih[j], biz = bih[j + H], bin = bih[j + 2 * H];
    float bhr = bhh[j], bhz = bhh[j + H], bhn = bhh[j + 2 * H];
    float2 hp2 = *(const float2*)(g_hT + j * B + lane * 2);

    float hn_out[2];
    #pragma unroll
    for (int d = 0; d < 2; d++) {
        int bb = lane * 2 + d;
        float gir = s_px[0][0][bb] + s_px[1][0][bb] + s_px[2][0][bb] + s_px[3][0][bb] + bir;
        float giz = s_px[0][1][bb] + s_px[1][1][bb] + s_px[2][1][bb] + s_px[3][1][bb] + biz;
        float gin = s_px[0][2][bb] + s_px[1][2][bb] + s_px[2][2][bb] + s_px[3][2][bb] + bin;
        float ghr = s_px[4][0][bb] + s_px[5][0][bb] + s_px[6][0][bb] + s_px[7][0][bb] + bhr;
        float ghz = s_px[4][1][bb] + s_px[5][1][bb] + s_px[6][1][bb] + s_px[7][1][bb] + bhz;
        float ghn = s_px[4][2][bb] + s_px[5][2][bb] + s_px[6][2][bb] + s_px[7][2][bb] + bhn;
        float r = 1.f / (1.f + __expf(-(gir + ghr)));
        float z = 1.f / (1.f + __expf(-(giz + ghz)));
        float n = tanhf(gin + r * ghn);
        float hprev = d ? hp2.y : hp2.x;
        hn_out[d] = (1.f - z) * n + z * hprev;
    }
    *(float2*)(g_yT + j * B + lane * 2) = make_float2(hn_out[0], hn_out[1]);
    if (out_h) {
        out_h[(lane * 2 + 0) * H + j] = hn_out[0];
        out_h[(lane * 2 + 1) * H + j] = hn_out[1];
    }
}

// ---------------- K7-v7: logits GEMM, 8v x 8b tile, k-split x2, 2 blocks/SM -------
// Grid 250 = 125 v-tiles x 2 k-halves; 256 threads. y half (64KB, bank-swizzled)
// + W double buffer (2 x 17KB). Partials summed by per-v-tile finisher.
#define SOP7 257
__global__ __launch_bounds__(256, 2) void k7_logits(const float* __restrict__ outW,
                                                    const float* __restrict__ outb,
                                                    float* __restrict__ dout)
{
    extern __shared__ float sm[];
    float* s_y = sm;                             // 16384 floats (64KB), swizzled
    float* s_w = sm + 16384;                     // 2 x 4352 floats (34.8KB)
    int tid = threadIdx.x;
    int vt = blockIdx.x >> 1;
    int half = blockIdx.x & 1;
    int v0b = vt * VT7;
    int kb = half * KH;

    unsigned syb = (unsigned)__cvta_generic_to_shared(s_y);
    unsigned swb = (unsigned)__cvta_generic_to_shared(s_w);

    // W chunk staging: 4096 scalars, 16/thread, 4-byte cp.async
    #define K7_ISSUE_W(cc, buf) do {                                             \
        int _c = (cc), _bf = (buf);                                              \
        _Pragma("unroll")                                                        \
        for (int t = 0; t < 16; t++) {                                           \
            int idx = tid + 256 * t;                                             \
            int row = idx >> 4, kk = idx & 15;                                   \
            cpasync4(swb + (unsigned)(_bf * WBUF7 + row * WP7 + kk) * 4,         \
                     outW + (size_t)(v0b + row) * H2 + kb + _c * KCH + kk);      \
        }                                                                        \
    } while (0)

    // prologue: y half (4096 f4, swizzled) + W chunk 0 in one group
    #pragma unroll
    for (int t = 0; t < 16; t++) {
        int idx = tid + 256 * t;                 // f4 index
        int k = idx >> 4, f4 = idx & 15;
        int swz = (f4 & 14) | ((f4 ^ (f4 >> 3)) & 1);   // XOR 16B-half with bg>>2
        cpasync16(syb + (unsigned)(k * 16 + swz) * 16,
                  g_yT + (size_t)(kb + k) * 64 + f4 * 4);
    }
    K7_ISSUE_W(0, 0);
    CP_COMMIT();

    int bg = tid & 7;                            // 8 b-groups of 8
    int tv = tid >> 3;                           // 32 v-groups of 8
    int vl = tv * 8;
    int b0 = bg * 8;
    int sw = (bg >> 2) & 1;
    int offA = sw * 4, offB = 4 - offA;          // swizzled 16B halves; ta=pairs{0,1}

    ull acc[8][4];
    #pragma unroll
    for (int i = 0; i < 8; i++)
        #pragma unroll
        for (int p = 0; p < 4; p++) acc[i][p] = 0ull;

    for (int c = 0; c < NCH7; c++) {
        CP_WAIT0();
        __syncthreads();                         // all past chunk c-1 compute
        if (c + 1 < NCH7) { K7_ISSUE_W(c + 1, (c + 1) & 1); CP_COMMIT(); }

        const float* wb = s_w + (c & 1) * WBUF7;
        #pragma unroll 4
        for (int kk = 0; kk < KCH; kk++) {
            int k = c * KCH + kk;
            const float* yr = s_y + k * 64 + b0;
            ulonglong2 ta = *(const ulonglong2*)(yr + offA);  // b-pairs {0,1}
            ulonglong2 tc = *(const ulonglong2*)(yr + offB);  // b-pairs {2,3}
            #pragma unroll
            for (int i = 0; i < 8; i++) {
                ull w2 = pack2(wb[(vl + i) * WP7 + kk]);
                acc[i][0] = fma2(acc[i][0], w2, ta.x);
                acc[i][1] = fma2(acc[i][1], w2, ta.y);
                acc[i][2] = fma2(acc[i][2], w2, tc.x);
                acc[i][3] = fma2(acc[i][3], w2, tc.y);
            }
        }
    }
    __syncthreads();                             // all reads of s_y/s_w done

    // stage partial 64b x 256v (pitch 257), no bias yet
    float* s_out = sm;                           // 64*257 = 16448 <= 25088 floats
    #pragma unroll
    for (int i = 0; i < 8; i++) {
        int v = vl + i;
        #pragma unroll
        for (int p = 0; p < 4; p++) {
            s_out[(b0 + 2 * p + 0) * SOP7 + v] = lo32(acc[i][p]);
            s_out[(b0 + 2 * p + 1) * SOP7 + v] = hi32(acc[i][p]);
        }
    }
    __syncthreads();

    // coalesced partial write: g_part[blk][b][v], 4096 f4, 16/thread
    float4* gp = (float4*)(g_part + (size_t)blockIdx.x * (VT7 * B));
    #pragma unroll
    for (int t = 0; t < 16; t++) {
        int i = tid + 256 * t;
        int v4 = i & 63, b = i >> 6;
        const float* s = s_out + b * SOP7 + v4 * 4;
        gp[i] = make_float4(s[0], s[1], s[2], s[3]);
    }

    // per-v-tile finisher: sum halves + bias -> logits + lse partials
    __shared__ int s_last;
    __threadfence();
    __syncthreads();
    if (tid == 0) s_last = (atomicAdd(&g_cntV[vt], 1) == 1) ? 1 : 0;
    __syncthreads();
    if (!s_last) return;

    const float4* pA = (const float4*)(g_part + (size_t)(vt * 2 + 0) * (VT7 * B));
    const float4* pB = (const float4*)(g_part + (size_t)(vt * 2 + 1) * (VT7 * B));
    #pragma unroll
    for (int t = 0; t < 16; t++) {
        int i = tid + 256 * t;
        int v4 = i & 63, b = i >> 6;
        float4 a = pA[i], bb = pB[i];
        float4 bi = *(const float4*)(outb + v0b + v4 * 4);
        float4 r = make_float4(a.x + bb.x + bi.x, a.y + bb.y + bi.y,
                               a.z + bb.z + bi.z, a.w + bb.w + bi.w);
        *(float4*)(g_logits + (size_t)b * V + v0b + v4 * 4) = r;
        float* s = s_out + b * SOP7 + v4 * 4;
        s[0] = r.x; s[1] = r.y; s[2] = r.z; s[3] = r.w;
    }
    __syncthreads();

    // lse partials: 4 threads per b, 64 v each
    int bq = tid >> 2, i4 = tid & 3;
    {
        const float* rr = s_out + bq * SOP7 + i4 * 64;
        float m = -INFINITY;
        #pragma unroll
        for (int j = 0; j < 64; j++) m = fmaxf(m, rr[j]);
        m = fmaxf(m, __shfl_xor_sync(0xffffffffu, m, 1));
        m = fmaxf(m, __shfl_xor_sync(0xffffffffu, m, 2));
        float s = 0.f;
        #pragma unroll
        for (int j = 0; j < 64; j++) s += __expf(rr[j] - m);
        s += __shfl_xor_sync(0xffffffffu, s, 1);
        s += __shfl_xor_sync(0xffffffffu, s, 2);
        if (i4 == 0) {
            g_lpm[bq * 128 + vt] = m;
            g_lps[bq * 128 + vt] = s;
        }
    }

    // last finisher merges lse
    __shared__ int s_fin;
    __threadfence();
    __syncthreads();
    if (tid == 0) s_fin = (atomicAdd(&g_cnt7, 1) == NB7V - 1) ? 1 : 0;
    __syncthreads();
    if (!s_fin) return;

    float m = -INFINITY;
    for (int i = i4; i < NB7V; i += 4) m = fmaxf(m, g_lpm[bq * 128 + i]);
    m = fmaxf(m, __shfl_xor_sync(0xffffffffu, m, 1));
    m = fmaxf(m, __shfl_xor_sync(0xffffffffu, m, 2));
    float s = 0.f;
    for (int i = i4; i < NB7V; i += 4)
        s += g_lps[bq * 128 + i] * __expf(g_lpm[bq * 128 + i] - m);
    s += __shfl_xor_sync(0xffffffffu, s, 1);
    s += __shfl_xor_sync(0xffffffffu, s, 2);
    if (i4 == 0) g_lse[bq] = m + logf(s);
}

// ---------------- K8w: out = logits - lse[b] ---------------------------------------
__global__ void k8w_write(float* __restrict__ out)
{
    int idx = blockIdx.x * 256 + threadIdx.x;   // float4 index
    int b = idx / (V / 4);
    float lse = g_lse[b];
    float4 v = ((const float4*)g_logits)[idx];
    v.x -= lse; v.y -= lse; v.z -= lse; v.w -= lse;
    ((float4*)out)[idx] = v;
}

// ---------------- host launch ------------------------------------------------------
extern "C" void kernel_launch(void* const* d_in, const int* in_sizes, int n_in,
                              void* d_out, int out_size)
{
    int s = (n_in >= 14 && in_sizes[3] == 1) ? 0 : -1;
    const int*   input    = (const int*)  d_in[0];
    const float* hidden   = (const float*)d_in[1];
    const float* enc      = (const float*)d_in[2];
    const float* emb      = (const float*)d_in[4 + s];
    const float* attn_W   = (const float*)d_in[5 + s];
    const float* attn_b   = (const float*)d_in[6 + s];
    const float* flatten  = (const float*)d_in[7 + s];
    const float* Wih      = (const float*)d_in[8 + s];
    const float* Whh      = (const float*)d_in[9 + s];
    const float* bih      = (const float*)d_in[10 + s];
    const float* bhh      = (const float*)d_in[11 + s];
    const float* outW     = (const float*)d_in[12 + s];
    const float* outb     = (const float*)d_in[13 + s];

    float* dout     = (float*)d_out;
    float* out_h    = (out_size >= B * V + B * H) ? dout + B * V : nullptr;
    float* out_attn = (out_size >= B * V + B * H + B * L) ? dout + B * V + B * H : nullptr;

    k0_prep<<<9, 512>>>(attn_W, attn_b, flatten, hidden, input, emb);

    int smem_kA = (16384 + 256 + 32 + 32 + 16 + 4) * (int)sizeof(float);  // ~66.9KB
    cudaFuncSetAttribute(kA_attn, cudaFuncAttributeMaxDynamicSharedMemorySize, smem_kA);
    kA_attn<<<B * NG, 256, smem_kA>>>(enc, out_attn);

    k56_gru<<<256, 256>>>(Wih, Whh, bih, bhh, out_h);

    int smem_k7 = (16384 + 2 * WBUF7) * (int)sizeof(float);               // 100352 B
    cudaFuncSetAttribute(k7_logits, cudaFuncAttributeMaxDynamicSharedMemorySize, smem_k7);
    k7_logits<<<NB7V * 2, 256, smem_k7>>>(outW, outb, dout);

    k8w_write<<<(B * V / 4) / 256, 256>>>(dout);
}

// round 16
// speedup vs baseline: 1.3461x; 1.0277x over previous
#include <cuda_runtime.h>
#include <math.h>

// Problem dims
#define H   256
#define H2  512
#define B   64
#define L   2048
#define V   32000
#define NG  8               // kA: groups per b
#define NCHG 8              // kA: chunks per group (32 l each)
#define NB7V 250            // k7: v tiles
#define VT7 128             // k7: v per tile
#define KH  128             // k7: k per quarter
#define KCH 16              // k7: k per W chunk
#define NCH7 8              // k7: chunks per quarter
#define WP7 17
#define WBUF7 (128 * 17)    // 2176 floats

typedef unsigned long long ull;

// ---------------- scratch (device globals) ----------------------------------------
__device__ __align__(16) float g_w2p[8][H2];
__device__ __align__(16) float g_w2[H2];
__device__ float g_bias;
__device__ __align__(16) float g_ehb[B];
__device__ __align__(16) float g_attn[B * L];        // exp(energy), unnormalized
__device__ __align__(16) float g_ps[B * NG];         // group exp-sums
__device__ __align__(16) float g_ctxp[B * NG * H];   // unnormalized partial ctx
__device__ __align__(16) float g_xT[H2 * B];         // [emb; ctx] transposed [k][b]
__device__ __align__(16) float g_hT[H * B];          // hidden transposed [k][b]
__device__ __align__(16) float g_yT[H2 * B];         // [h_new; ctx] transposed [k][b]
__device__ __align__(16) float g_part[1000 * VT7 * B]; // k7 quarter-partials
__device__ __align__(16) float g_logits[B * V];
__device__ __align__(16) float g_lpm[B * 256];
__device__ __align__(16) float g_lps[B * 256];
__device__ __align__(16) float g_lse[B];
__device__ int g_cnt0;
__device__ int g_cntA[B];
__device__ int g_cntV[NB7V];
__device__ int g_cnt7;

__device__ __forceinline__ ull fma2(ull a, ull x, ull c) {
    asm("fma.rn.f32x2 %0, %1, %2, %3;" : "=l"(a) : "l"(x), "l"(c), "l"(a));
    return a;
}
__device__ __forceinline__ ull pack2(float w) {
    ull r;
    asm("mov.b64 %0, {%1, %1};" : "=l"(r) : "f"(w));
    return r;
}
__device__ __forceinline__ float lo32(ull a) { return __uint_as_float((unsigned)(a & 0xffffffffull)); }
__device__ __forceinline__ float hi32(ull a) { return __uint_as_float((unsigned)(a >> 32)); }
__device__ __forceinline__ void cpasync16(unsigned smem, const void* g) {
    asm volatile("cp.async.ca.shared.global [%0], [%1], 16;" :: "r"(smem), "l"(g));
}
__device__ __forceinline__ void cpasync4(unsigned smem, const void* g) {
    asm volatile("cp.async.ca.shared.global [%0], [%1], 4;" :: "r"(smem), "l"(g));
}
#define CP_COMMIT() asm volatile("cp.async.commit_group;")
#define CP_WAIT0()  asm volatile("cp.async.wait_group 0;")

// ---------------- K0: w2 partials + bias + transposes + last-block combine --------
__global__ void k0_prep(const float* __restrict__ attn_W,
                        const float* __restrict__ attn_b,
                        const float* __restrict__ flatten,
                        const float* __restrict__ hidden,
                        const int*   __restrict__ input,
                        const float* __restrict__ emb_table)
{
    __shared__ float s_f[32];
    __shared__ float red[512];
    __shared__ float s_wh[H];
    __shared__ int s_last;
    int blk = blockIdx.x, tid = threadIdx.x;    // 512 threads, 9 blocks

    if (blk < 8) {
        if (tid < 32) s_f[tid] = flatten[blk * 32 + tid];
        __syncthreads();
        float acc = 0.f;
        #pragma unroll 8
        for (int i = 0; i < 32; i++)
            acc += attn_W[(size_t)(blk * 32 + i) * H2 + tid] * s_f[i];
        g_w2p[blk][tid] = acc;
    } else {
        red[tid] = (tid < H) ? flatten[tid] * attn_b[tid] : 0.f;
        __syncthreads();
        for (int s = 256; s > 0; s >>= 1) {
            if (tid < s) red[tid] += red[tid + s];
            __syncthreads();
        }
        if (tid == 0) g_bias = red[0];
        if (tid == 1) g_cnt7 = 0;
        if (tid >= 64 && tid < 128) g_cntA[tid - 64] = 0;
        if (tid >= 128 && tid < 128 + NB7V) g_cntV[tid - 128] = 0;
        for (int idx = tid; idx < B * H; idx += 512) {
            int b = idx >> 8, j = idx & 255;
            g_xT[j * B + b] = emb_table[(size_t)input[b] * H + j];
            g_hT[j * B + b] = hidden[idx];
        }
    }

    __threadfence();
    __syncthreads();
    if (tid == 0) s_last = (atomicAdd(&g_cnt0, 1) == 8) ? 1 : 0;
    __syncthreads();
    if (!s_last) return;

    float w = 0.f;
    #pragma unroll
    for (int k = 0; k < 8; k++) w += g_w2p[k][tid];
    g_w2[tid] = w;
    if (tid < H) s_wh[tid] = w;
    __syncthreads();

    int wid = tid >> 5, lane = tid & 31;        // 16 warps x 4 b
    float bias = g_bias;
    #pragma unroll
    for (int i = 0; i < 4; i++) {
        int b = wid * 4 + i;
        float a = 0.f;
        #pragma unroll
        for (int c = 0; c < 8; c++) {
            int k = c * 32 + lane;
            a += hidden[b * H + k] * s_wh[k];
        }
        #pragma unroll
        for (int o = 16; o > 0; o >>= 1) a += __shfl_down_sync(0xffffffffu, a, o);
        if (lane == 0) g_ehb[b] = a + bias;
    }
    if (tid == 0) g_cnt0 = 0;                   // reset for graph replay
}

// ---------------- KA-v4: energies + exp (no max shift; |e| bounded) + ctx ---------
__global__ __launch_bounds__(256) void kA_attn(const float* __restrict__ enc,
                                               float* __restrict__ out_attn)
{
    extern __shared__ float sm[];
    float* s_w2 = sm + 16384;        // 256
    float* s_w  = s_w2 + H;          // 32 (chunk exp weights)
    float* s_iv = s_w + 32;          // [0]=inv
    int*   s_fl = (int*)(s_iv + 2);

    int b = blockIdx.x >> 3;
    int g = blockIdx.x & 7;
    int tid = threadIdx.x;
    int wid = tid >> 5, lane = tid & 31;

    unsigned tb = (unsigned)__cvta_generic_to_shared(sm);
    const float4* src0 = (const float4*)(enc + (size_t)b * H);

    // prologue: chunk 0 into buf 0
    {
        int l0 = g * (NCHG * 32);
        #pragma unroll
        for (int i = 0; i < 8; i++) {
            int idx = tid + 256 * i;
            int row = idx >> 6, col = idx & 63;
            cpasync16(tb + (unsigned)idx * 16, src0 + (size_t)(l0 + row) * 4096 + col);
        }
        CP_COMMIT();
    }
    s_w2[tid] = g_w2[H + tid];
    float ehb = g_ehb[b];
    float ctx_acc = 0.f;
    float s_run = 0.f;                          // warp 0 lanes: partial sums

    for (int i = 0; i < NCHG; i++) {
        CP_WAIT0();
        __syncthreads();
        if (i + 1 < NCHG) {
            int l0 = g * (NCHG * 32) + (i + 1) * 32;
            unsigned dst = tb + (unsigned)(((i + 1) & 1) * 8192) * 4;
            #pragma unroll
            for (int t = 0; t < 8; t++) {
                int idx = tid + 256 * t;
                int row = idx >> 6, col = idx & 63;
                cpasync16(dst + (unsigned)idx * 16, src0 + (size_t)(l0 + row) * 4096 + col);
            }
            CP_COMMIT();
        }

        float* tile = sm + (i & 1) * 8192;
        int l0 = g * (NCHG * 32) + i * 32;

        #pragma unroll
        for (int r = 0; r < 4; r++) {
            int l = wid * 4 + r;
            const float4* tr = (const float4*)(tile + l * H);
            const float4* w4 = (const float4*)s_w2;
            float4 t0 = tr[lane],      w0 = w4[lane];
            float4 t1 = tr[32 + lane], w1 = w4[32 + lane];
            float a = t0.x * w0.x + t0.y * w0.y + t0.z * w0.z + t0.w * w0.w
                    + t1.x * w1.x + t1.y * w1.y + t1.z * w1.z + t1.w * w1.w;
            #pragma unroll
            for (int o = 16; o > 0; o >>= 1) a += __shfl_down_sync(0xffffffffu, a, o);
            if (lane == 0) {
                float w = __expf(a + ehb);
                s_w[l] = w;
                g_attn[b * L + l0 + l] = w;
            }
        }
        __syncthreads();

        if (wid == 0) s_run += s_w[lane];

        float a0 = 0.f, a1 = 0.f, a2 = 0.f, a3 = 0.f;
        #pragma unroll
        for (int l = 0; l < 32; l += 4) {
            a0 += s_w[l + 0] * tile[(l + 0) * H + tid];
            a1 += s_w[l + 1] * tile[(l + 1) * H + tid];
            a2 += s_w[l + 2] * tile[(l + 2) * H + tid];
            a3 += s_w[l + 3] * tile[(l + 3) * H + tid];
        }
        ctx_acc += (a0 + a1) + (a2 + a3);
    }

    g_ctxp[(size_t)(b * NG + g) * H + tid] = ctx_acc;
    if (wid == 0) {
        #pragma unroll
        for (int o = 16; o > 0; o >>= 1) s_run += __shfl_xor_sync(0xffffffffu, s_run, o);
        if (lane == 0) g_ps[b * NG + g] = s_run;
    }

    __threadfence();
    __syncthreads();
    if (tid == 0) s_fl[0] = (atomicAdd(&g_cntA[b], 1) == NG - 1) ? 1 : 0;
    __syncthreads();
    if (!s_fl[0]) return;

    if (tid == 0) {
        float ssum = 0.f;
        #pragma unroll
        for (int gg = 0; gg < NG; gg++) ssum += g_ps[b * NG + gg];
        s_iv[0] = 1.f / ssum;
    }
    __syncthreads();
    float inv = s_iv[0];

    float acc = 0.f;
    #pragma unroll
    for (int gg = 0; gg < NG; gg++)
        acc += g_ctxp[(size_t)(b * NG + gg) * H + tid];
    float ctxv = acc * inv;
    g_xT[(H + tid) * B + b] = ctxv;
    g_yT[(H + tid) * B + b] = ctxv;

    if (out_attn)
        for (int l = tid; l < L; l += 256)
            out_attn[b * L + l] = g_attn[b * L + l] * inv;
}

// ---------------- K56: GRU, block per j, 8 warps split k, lanes = b-pairs ---------
__global__ __launch_bounds__(256) void k56_gru(const float* __restrict__ Wih,
                                               const float* __restrict__ Whh,
                                               const float* __restrict__ bih,
                                               const float* __restrict__ bhh,
                                               float* __restrict__ out_h)
{
    __shared__ float s_px[8][3][64];            // warp, gate, b
    int j = blockIdx.x;                         // 0..255
    int tid = threadIdx.x;
    int wid = tid >> 5, lane = tid & 31;

    ull ar = 0, az = 0, an = 0;
    if (wid < 4) {
        int k0 = wid * 128;
        const float* wr = Wih + (size_t)j * H2 + k0;
        const float* wz = Wih + (size_t)(j + H) * H2 + k0;
        const float* wn = Wih + (size_t)(j + 2 * H) * H2 + k0;
        const float* xp = g_xT + k0 * B + lane * 2;
        #pragma unroll 8
        for (int k = 0; k < 128; k++) {
            ull x2 = *(const ull*)(xp + k * B);
            ar = fma2(ar, pack2(wr[k]), x2);
            az = fma2(az, pack2(wz[k]), x2);
            an = fma2(an, pack2(wn[k]), x2);
        }
    } else {
        int k0 = (wid - 4) * 64;
        const float* wr = Whh + (size_t)j * H + k0;
        const float* wz = Whh + (size_t)(j + H) * H + k0;
        const float* wn = Whh + (size_t)(j + 2 * H) * H + k0;
        const float* hp = g_hT + k0 * B + lane * 2;
        #pragma unroll 8
        for (int k = 0; k < 64; k++) {
            ull h2 = *(const ull*)(hp + k * B);
            ar = fma2(ar, pack2(wr[k]), h2);
            az = fma2(az, pack2(wz[k]), h2);
            an = fma2(an, pack2(wn[k]), h2);
        }
    }
    s_px[wid][0][lane * 2] = lo32(ar); s_px[wid][0][lane * 2 + 1] = hi32(ar);
    s_px[wid][1][lane * 2] = lo32(az); s_px[wid][1][lane * 2 + 1] = hi32(az);
    s_px[wid][2][lane * 2] = lo32(an); s_px[wid][2][lane * 2 + 1] = hi32(an);
    __syncthreads();

    if (wid != 0) return;
    float bir = bih[j], biz = bih[j + H], bin = bih[j + 2 * H];
    float bhr = bhh[j], bhz = bhh[j + H], bhn = bhh[j + 2 * H];
    float2 hp2 = *(const float2*)(g_hT + j * B + lane * 2);

    float hn_out[2];
    #pragma unroll
    for (int d = 0; d < 2; d++) {
        int bb = lane * 2 + d;
        float gir = s_px[0][0][bb] + s_px[1][0][bb] + s_px[2][0][bb] + s_px[3][0][bb] + bir;
        float giz = s_px[0][1][bb] + s_px[1][1][bb] + s_px[2][1][bb] + s_px[3][1][bb] + biz;
        float gin = s_px[0][2][bb] + s_px[1][2][bb] + s_px[2][2][bb] + s_px[3][2][bb] + bin;
        float ghr = s_px[4][0][bb] + s_px[5][0][bb] + s_px[6][0][bb] + s_px[7][0][bb] + bhr;
        float ghz = s_px[4][1][bb] + s_px[5][1][bb] + s_px[6][1][bb] + s_px[7][1][bb] + bhz;
        float ghn = s_px[4][2][bb] + s_px[5][2][bb] + s_px[6][2][bb] + s_px[7][2][bb] + bhn;
        float r = 1.f / (1.f + __expf(-(gir + ghr)));
        float z = 1.f / (1.f + __expf(-(giz + ghz)));
        float n = tanhf(gin + r * ghn);
        float hprev = d ? hp2.y : hp2.x;
        hn_out[d] = (1.f - z) * n + z * hprev;
    }
    *(float2*)(g_yT + j * B + lane * 2) = make_float2(hn_out[0], hn_out[1]);
    if (out_h) {
        out_h[(lane * 2 + 0) * H + j] = hn_out[0];
        out_h[(lane * 2 + 1) * H + j] = hn_out[1];
    }
}

// ---------------- K7-v9: logits GEMM, 128v x 64b tile, k-split x4 -----------------
// Grid 1000 = 250 v-tiles x 4 k-quarters; 256 threads; tile 4v x 8b covers
// the FULL 128 v (R15 bug: covered only half of a 256-v tile). smem 50KB.
#define SOP7 129
__global__ __launch_bounds__(256, 3) void k7_logits(const float* __restrict__ outW,
                                                    const float* __restrict__ outb)
{
    extern __shared__ float sm[];
    float* s_y = sm;                             // 8192 floats (32KB), swizzled
    float* s_w = sm + 8192;                      // 2 x 2176 floats (17.4KB)
    int tid = threadIdx.x;
    int vt = blockIdx.x >> 2;
    int quarter = blockIdx.x & 3;
    int v0b = vt * VT7;
    int kb = quarter * KH;

    unsigned syb = (unsigned)__cvta_generic_to_shared(s_y);
    unsigned swb = (unsigned)__cvta_generic_to_shared(s_w);

    // W chunk staging: 2048 scalars (128 rows x 16 k), 8/thread
    #define K7_ISSUE_W(cc, buf) do {                                             \
        int _c = (cc), _bf = (buf);                                              \
        _Pragma("unroll")                                                        \
        for (int t = 0; t < 8; t++) {                                            \
            int idx = tid + 256 * t;                                             \
            int row = idx >> 4, kk = idx & 15;                                   \
            cpasync4(swb + (unsigned)(_bf * WBUF7 + row * WP7 + kk) * 4,         \
                     outW + (size_t)(v0b + row) * H2 + kb + _c * KCH + kk);      \
        }                                                                        \
    } while (0)

    // prologue: y quarter (2048 f4, swizzled, 8/thread) + W chunk 0
    #pragma unroll
    for (int t = 0; t < 8; t++) {
        int idx = tid + 256 * t;                 // f4 index
        int k = idx >> 4, f4 = idx & 15;
        int swz = (f4 & 14) | ((f4 ^ (f4 >> 3)) & 1);
        cpasync16(syb + (unsigned)(k * 16 + swz) * 16,
                  g_yT + (size_t)(kb + k) * 64 + f4 * 4);
    }
    K7_ISSUE_W(0, 0);
    CP_COMMIT();

    int bg = tid & 7;                            // 8 b-groups of 8
    int tv = tid >> 3;                           // 32 v-groups of 4 -> 128 v total
    int vl = tv * 4;
    int b0 = bg * 8;
    int sw = (bg >> 2) & 1;
    int offA = sw * 4, offB = 4 - offA;

    ull acc[4][4];
    #pragma unroll
    for (int i = 0; i < 4; i++)
        #pragma unroll
        for (int p = 0; p < 4; p++) acc[i][p] = 0ull;

    for (int c = 0; c < NCH7; c++) {
        CP_WAIT0();
        __syncthreads();
        if (c + 1 < NCH7) { K7_ISSUE_W(c + 1, (c + 1) & 1); CP_COMMIT(); }

        const float* wb = s_w + (c & 1) * WBUF7;
        #pragma unroll 4
        for (int kk = 0; kk < KCH; kk++) {
            int k = c * KCH + kk;
            const float* yr = s_y + k * 64 + b0;
            ulonglong2 ta = *(const ulonglong2*)(yr + offA);
            ulonglong2 tc = *(const ulonglong2*)(yr + offB);
            #pragma unroll
            for (int i = 0; i < 4; i++) {
                ull w2 = pack2(wb[(vl + i) * WP7 + kk]);
                acc[i][0] = fma2(acc[i][0], w2, ta.x);
                acc[i][1] = fma2(acc[i][1], w2, ta.y);
                acc[i][2] = fma2(acc[i][2], w2, tc.x);
                acc[i][3] = fma2(acc[i][3], w2, tc.y);
            }
        }
    }
    __syncthreads();

    // stage partial 64b x 128v (pitch 129)
    float* s_out = sm;                           // 64*129 = 8256 <= 12544 floats
    #pragma unroll
    for (int i = 0; i < 4; i++) {
        int v = vl + i;
        #pragma unroll
        for (int p = 0; p < 4; p++) {
            s_out[(b0 + 2 * p + 0) * SOP7 + v] = lo32(acc[i][p]);
            s_out[(b0 + 2 * p + 1) * SOP7 + v] = hi32(acc[i][p]);
        }
    }
    __syncthreads();

    // coalesced partial write: g_part[blk][b][v], 2048 f4, 8/thread
    float4* gp = (float4*)(g_part + (size_t)blockIdx.x * (VT7 * B));
    #pragma unroll
    for (int t = 0; t < 8; t++) {
        int i = tid + 256 * t;
        int v4 = i & 31, b = i >> 5;
        const float* s = s_out + b * SOP7 + v4 * 4;
        gp[i] = make_float4(s[0], s[1], s[2], s[3]);
    }

    // per-v-tile finisher (last quarter): sum 4 partials + bias -> logits, lse
    __shared__ int s_last;
    __threadfence();
    __syncthreads();
    if (tid == 0) s_last = (atomicAdd(&g_cntV[vt], 1) == 3) ? 1 : 0;
    __syncthreads();
    if (!s_last) return;

    const float4* p0 = (const float4*)(g_part + (size_t)(vt * 4 + 0) * (VT7 * B));
    const float4* p1 = (const float4*)(g_part + (size_t)(vt * 4 + 1) * (VT7 * B));
    const float4* p2 = (const float4*)(g_part + (size_t)(vt * 4 + 2) * (VT7 * B));
    const float4* p3 = (const float4*)(g_part + (size_t)(vt * 4 + 3) * (VT7 * B));
    #pragma unroll
    for (int t = 0; t < 8; t++) {
        int i = tid + 256 * t;
        int v4 = i & 31, b = i >> 5;
        float4 a = p0[i], c = p1[i], d = p2[i], e = p3[i];
        float4 bi = *(const float4*)(outb + v0b + v4 * 4);
        float4 r = make_float4((a.x + c.x) + (d.x + e.x) + bi.x,
                               (a.y + c.y) + (d.y + e.y) + bi.y,
                               (a.z + c.z) + (d.z + e.z) + bi.z,
                               (a.w + c.w) + (d.w + e.w) + bi.w);
        *(float4*)(g_logits + (size_t)b * V + v0b + v4 * 4) = r;
        float* s = s_out + b * SOP7 + v4 * 4;
        s[0] = r.x; s[1] = r.y; s[2] = r.z; s[3] = r.w;
    }
    __syncthreads();

    // lse partials: 4 threads per b, 32 v each
    int bq = tid >> 2, i4 = tid & 3;
    {
        const float* rr = s_out + bq * SOP7 + i4 * 32;
        float m = -INFINITY;
        #pragma unroll
        for (int j = 0; j < 32; j++) m = fmaxf(m, rr[j]);
        m = fmaxf(m, __shfl_xor_sync(0xffffffffu, m, 1));
        m = fmaxf(m, __shfl_xor_sync(0xffffffffu, m, 2));
        float s = 0.f;
        #pragma unroll
        for (int j = 0; j < 32; j++) s += __expf(rr[j] - m);
        s += __shfl_xor_sync(0xffffffffu, s, 1);
        s += __shfl_xor_sync(0xffffffffu, s, 2);
        if (i4 == 0) {
            g_lpm[bq * 256 + vt] = m;
            g_lps[bq * 256 + vt] = s;
        }
    }

    // last finisher merges lse
    __shared__ int s_fin;
    __threadfence();
    __syncthreads();
    if (tid == 0) s_fin = (atomicAdd(&g_cnt7, 1) == NB7V - 1) ? 1 : 0;
    __syncthreads();
    if (!s_fin) return;

    float m = -INFINITY;
    for (int i = i4; i < NB7V; i += 4) m = fmaxf(m, g_lpm[bq * 256 + i]);
    m = fmaxf(m, __shfl_xor_sync(0xffffffffu, m, 1));
    m = fmaxf(m, __shfl_xor_sync(0xffffffffu, m, 2));
    float s = 0.f;
    for (int i = i4; i < NB7V; i += 4)
        s += g_lps[bq * 256 + i] * __expf(g_lpm[bq * 256 + i] - m);
    s += __shfl_xor_sync(0xffffffffu, s, 1);
    s += __shfl_xor_sync(0xffffffffu, s, 2);
    if (i4 == 0) g_lse[bq] = m + logf(s);
}

// ---------------- K8w: out = logits - lse[b] ---------------------------------------
__global__ void k8w_write(float* __restrict__ out)
{
    int idx = blockIdx.x * 256 + threadIdx.x;   // float4 index
    int b = idx / (V / 4);
    float lse = g_lse[b];
    float4 v = ((const float4*)g_logits)[idx];
    v.x -= lse; v.y -= lse; v.z -= lse; v.w -= lse;
    ((float4*)out)[idx] = v;
}

// ---------------- host launch ------------------------------------------------------
extern "C" void kernel_launch(void* const* d_in, const int* in_sizes, int n_in,
                              void* d_out, int out_size)
{
    int s = (n_in >= 14 && in_sizes[3] == 1) ? 0 : -1;
    const int*   input    = (const int*)  d_in[0];
    const float* hidden   = (const float*)d_in[1];
    const float* enc      = (const float*)d_in[2];
    const float* emb      = (const float*)d_in[4 + s];
    const float* attn_W   = (const float*)d_in[5 + s];
    const float* attn_b   = (const float*)d_in[6 + s];
    const float* flatten  = (const float*)d_in[7 + s];
    const float* Wih      = (const float*)d_in[8 + s];
    const float* Whh      = (const float*)d_in[9 + s];
    const float* bih      = (const float*)d_in[10 + s];
    const float* bhh      = (const float*)d_in[11 + s];
    const float* outW     = (const float*)d_in[12 + s];
    const float* outb     = (const float*)d_in[13 + s];

    float* dout     = (float*)d_out;
    float* out_h    = (out_size >= B * V + B * H) ? dout + B * V : nullptr;
    float* out_attn = (out_size >= B * V + B * H + B * L) ? dout + B * V + B * H : nullptr;

    k0_prep<<<9, 512>>>(attn_W, attn_b, flatten, hidden, input, emb);

    int smem_kA = (16384 + 256 + 32 + 2 + 4) * (int)sizeof(float);    // ~66.7KB
    cudaFuncSetAttribute(kA_attn, cudaFuncAttributeMaxDynamicSharedMemorySize, smem_kA);
    kA_attn<<<B * NG, 256, smem_kA>>>(enc, out_attn);

    k56_gru<<<256, 256>>>(Wih, Whh, bih, bhh, out_h);

    int smem_k7 = (8192 + 2 * WBUF7) * (int)sizeof(float);            // 50176 B
    cudaFuncSetAttribute(k7_logits, cudaFuncAttributeMaxDynamicSharedMemorySize, smem_k7);
    k7_logits<<<NB7V * 4, 256, smem_k7>>>(outW, outb);

    k8w_write<<<(B * V / 4) / 256, 256>>>(dout);
}